// round 1
// baseline (speedup 1.0000x reference)
#include <cuda_runtime.h>
#include <cuda_fp16.h>

// QuantizedBatchNorm3d: x [8,64,32,64,64] fp32, weight[64], bias[64] -> y same shape.
// fake_quant(exp=5, sig=10, RNE) == IEEE fp16 round-trip for all reachable values.

#define NB        8
#define NC        64
#define SPATIAL   (32*64*64)            // 131072 = 2^17, per (n,c) slice
#define CPC       (NB*SPATIAL)          // 1048576 = 2^20 elements per channel
#define TOTAL_V4  (1 << 24)             // 2^26 elements / 4
#define BPC       32                    // reduce blocks per channel
#define RTHREADS  256

__device__ float  g_psum[NC * BPC];
__device__ float  g_psq [NC * BPC];
__device__ float4 g_params[NC];         // {mean_q, inv_std, w_q, b_q}

__device__ __forceinline__ float fq1(float v) {
    return __half2float(__float2half_rn(v));
}
__device__ __forceinline__ float2 fq2(float a, float b) {
    __half2 h = __float22half2_rn(make_float2(a, b));
    return __half22float2(h);
}

// ---------------- Pass 1: per-channel sum / sumsq of fake_quant(x) ----------------
__global__ void __launch_bounds__(RTHREADS) qbn_reduce(const float* __restrict__ x) {
    const int c   = blockIdx.y;
    const int bx  = blockIdx.x;
    const int tid = threadIdx.x;

    const int VEC_PER_N = SPATIAL / 4;          // 32768 float4 per (n,c) slice
    const int stride    = BPC * RTHREADS;       // 8192
    const int start     = bx * RTHREADS + tid;

    float s = 0.f, sq = 0.f;
    #pragma unroll
    for (int n = 0; n < NB; n++) {
        const float4* p = reinterpret_cast<const float4*>(
            x + (size_t)(n * NC + c) * SPATIAL);
        #pragma unroll
        for (int i = 0; i < VEC_PER_N / stride; i++) {   // 4 iters
            float4 v = p[start + i * stride];
            float2 a = fq2(v.x, v.y);
            float2 b = fq2(v.z, v.w);
            s  += (a.x + a.y) + (b.x + b.y);
            sq += a.x*a.x + a.y*a.y + b.x*b.x + b.y*b.y;
        }
    }

    // warp reduce
    #pragma unroll
    for (int o = 16; o > 0; o >>= 1) {
        s  += __shfl_down_sync(0xffffffffu, s,  o);
        sq += __shfl_down_sync(0xffffffffu, sq, o);
    }
    __shared__ float sh_s[RTHREADS / 32], sh_q[RTHREADS / 32];
    const int lane = tid & 31, w = tid >> 5;
    if (lane == 0) { sh_s[w] = s; sh_q[w] = sq; }
    __syncthreads();
    if (w == 0) {
        s  = (lane < RTHREADS / 32) ? sh_s[lane] : 0.f;
        sq = (lane < RTHREADS / 32) ? sh_q[lane] : 0.f;
        #pragma unroll
        for (int o = 4; o > 0; o >>= 1) {
            s  += __shfl_down_sync(0xffffffffu, s,  o);
            sq += __shfl_down_sync(0xffffffffu, sq, o);
        }
        if (lane == 0) {
            g_psum[c * BPC + bx] = s;
            g_psq [c * BPC + bx] = sq;
        }
    }
}

// ---------------- Pass 2: per-channel stats -> params ----------------
__global__ void qbn_finalize(const float* __restrict__ weight,
                             const float* __restrict__ bias) {
    const int c    = blockIdx.x;
    const int lane = threadIdx.x;   // 32 threads
    float s  = g_psum[c * BPC + lane];
    float sq = g_psq [c * BPC + lane];
    #pragma unroll
    for (int o = 16; o > 0; o >>= 1) {
        s  += __shfl_down_sync(0xffffffffu, s,  o);
        sq += __shfl_down_sync(0xffffffffu, sq, o);
    }
    if (lane == 0) {
        const float inv_n = 1.0f / (float)CPC;
        float mean = s * inv_n;                       // raw fp32 mean of x_q
        float var  = sq * inv_n - mean * mean;        // E[x^2] - mean^2
        float mean_q  = fq1(mean);
        float var_q   = fq1(var);
        float inv_std = 1.0f / sqrtf(var_q + 1e-5f);
        float w_q     = fq1(weight[c]);
        float b_q     = fq1(bias[c]);
        g_params[c] = make_float4(mean_q, inv_std, w_q, b_q);
    }
}

// ---------------- Pass 3: elementwise normalize + final quant ----------------
__global__ void __launch_bounds__(256) qbn_apply(const float* __restrict__ x,
                                                 float* __restrict__ out) {
    __shared__ float4 sp[NC];
    if (threadIdx.x < NC) sp[threadIdx.x] = g_params[threadIdx.x];
    __syncthreads();

    const float4* xin = reinterpret_cast<const float4*>(x);
    float4*       yo  = reinterpret_cast<float4*>(out);

    const int stride = gridDim.x * blockDim.x;
    for (int v = blockIdx.x * blockDim.x + threadIdx.x; v < TOTAL_V4; v += stride) {
        const int c = (v >> 15) & (NC - 1);     // SPATIAL/4 = 2^15 vec4 per slice
        const float4 p = sp[c];                 // {mean, inv_std, w, b}
        float4 xv = xin[v];
        float2 a = fq2(xv.x, xv.y);
        float2 b = fq2(xv.z, xv.w);
        float y0 = fmaf(p.z, (a.x - p.x) * p.y, p.w);
        float y1 = fmaf(p.z, (a.y - p.x) * p.y, p.w);
        float y2 = fmaf(p.z, (b.x - p.x) * p.y, p.w);
        float y3 = fmaf(p.z, (b.y - p.x) * p.y, p.w);
        float2 q0 = fq2(y0, y1);
        float2 q1 = fq2(y2, y3);
        yo[v] = make_float4(q0.x, q0.y, q1.x, q1.y);
    }
}

extern "C" void kernel_launch(void* const* d_in, const int* in_sizes, int n_in,
                              void* d_out, int out_size) {
    const float* x      = (const float*)d_in[0];
    const float* weight = (const float*)d_in[1];
    const float* bias   = (const float*)d_in[2];
    float* out = (float*)d_out;

    dim3 rgrid(BPC, NC);
    qbn_reduce  <<<rgrid, RTHREADS>>>(x);
    qbn_finalize<<<NC, 32>>>(weight, bias);
    qbn_apply   <<<2048, 256>>>(x, out);
}

// round 2
// speedup vs baseline: 1.0333x; 1.0333x over previous
#include <cuda_runtime.h>
#include <cuda_fp16.h>

// QuantizedBatchNorm3d: x [8,64,32,64,64] fp32, weight[64], bias[64] -> y same shape.
// fake_quant(exp=5, sig=10, RNE) == IEEE fp16 round-trip for all reachable values.
//
// R2: apply pass walks x BACKWARD to harvest the ~126MB tail of x that the
// reduce pass leaves resident in L2 (reduce reads n-major, n=0..7, so the
// upper half of x is read last). Streaming stores (stcs) keep output from
// evicting that tail; streaming loads (ldcs) mark x dead-after-read.

#define NB        8
#define NC        64
#define SPATIAL   (32*64*64)            // 131072 = 2^17, per (n,c) slice
#define CPC       (NB*SPATIAL)          // 1048576 = 2^20 elements per channel
#define TOTAL_V4  (1 << 24)             // 2^26 elements / 4
#define BPC       32                    // reduce blocks per channel
#define RTHREADS  256

__device__ float  g_psum[NC * BPC];
__device__ float  g_psq [NC * BPC];
__device__ float4 g_params[NC];         // {mean_q, inv_std, w_q, b_q}

__device__ __forceinline__ float fq1(float v) {
    return __half2float(__float2half_rn(v));
}
__device__ __forceinline__ float2 fq2(float a, float b) {
    __half2 h = __float22half2_rn(make_float2(a, b));
    return __half22float2(h);
}

// ---------------- Pass 1: per-channel sum / sumsq of fake_quant(x) ----------------
__global__ void __launch_bounds__(RTHREADS) qbn_reduce(const float* __restrict__ x) {
    const int c   = blockIdx.y;
    const int bx  = blockIdx.x;
    const int tid = threadIdx.x;

    const int VEC_PER_N = SPATIAL / 4;          // 32768 float4 per (n,c) slice
    const int stride    = BPC * RTHREADS;       // 8192
    const int start     = bx * RTHREADS + tid;

    float s = 0.f, sq = 0.f;
    #pragma unroll
    for (int n = 0; n < NB; n++) {
        const float4* p = reinterpret_cast<const float4*>(
            x + (size_t)(n * NC + c) * SPATIAL);
        #pragma unroll
        for (int i = 0; i < VEC_PER_N / stride; i++) {   // 4 iters
            float4 v = p[start + i * stride];
            float2 a = fq2(v.x, v.y);
            float2 b = fq2(v.z, v.w);
            s  += (a.x + a.y) + (b.x + b.y);
            sq += a.x*a.x + a.y*a.y + b.x*b.x + b.y*b.y;
        }
    }

    // warp reduce
    #pragma unroll
    for (int o = 16; o > 0; o >>= 1) {
        s  += __shfl_down_sync(0xffffffffu, s,  o);
        sq += __shfl_down_sync(0xffffffffu, sq, o);
    }
    __shared__ float sh_s[RTHREADS / 32], sh_q[RTHREADS / 32];
    const int lane = tid & 31, w = tid >> 5;
    if (lane == 0) { sh_s[w] = s; sh_q[w] = sq; }
    __syncthreads();
    if (w == 0) {
        s  = (lane < RTHREADS / 32) ? sh_s[lane] : 0.f;
        sq = (lane < RTHREADS / 32) ? sh_q[lane] : 0.f;
        #pragma unroll
        for (int o = 4; o > 0; o >>= 1) {
            s  += __shfl_down_sync(0xffffffffu, s,  o);
            sq += __shfl_down_sync(0xffffffffu, sq, o);
        }
        if (lane == 0) {
            g_psum[c * BPC + bx] = s;
            g_psq [c * BPC + bx] = sq;
        }
    }
}

// ---------------- Pass 2: per-channel stats -> params ----------------
__global__ void qbn_finalize(const float* __restrict__ weight,
                             const float* __restrict__ bias) {
    const int c    = blockIdx.x;
    const int lane = threadIdx.x;   // 32 threads
    float s  = g_psum[c * BPC + lane];
    float sq = g_psq [c * BPC + lane];
    #pragma unroll
    for (int o = 16; o > 0; o >>= 1) {
        s  += __shfl_down_sync(0xffffffffu, s,  o);
        sq += __shfl_down_sync(0xffffffffu, sq, o);
    }
    if (lane == 0) {
        const float inv_n = 1.0f / (float)CPC;
        float mean = s * inv_n;                       // raw fp32 mean of x_q
        float var  = sq * inv_n - mean * mean;        // E[x^2] - mean^2
        float mean_q  = fq1(mean);
        float var_q   = fq1(var);
        float inv_std = 1.0f / sqrtf(var_q + 1e-5f);
        float w_q     = fq1(weight[c]);
        float b_q     = fq1(bias[c]);
        g_params[c] = make_float4(mean_q, inv_std, w_q, b_q);
    }
}

// ---------------- Pass 3: elementwise normalize + final quant (backward walk) ----
__global__ void __launch_bounds__(256) qbn_apply(const float* __restrict__ x,
                                                 float* __restrict__ out) {
    __shared__ float4 sp[NC];
    if (threadIdx.x < NC) sp[threadIdx.x] = g_params[threadIdx.x];
    __syncthreads();

    const float4* xin = reinterpret_cast<const float4*>(x);
    float4*       yo  = reinterpret_cast<float4*>(out);

    const int stride = gridDim.x * blockDim.x;
    const int base   = blockIdx.x * blockDim.x + threadIdx.x;

    // Walk from the END of x toward the start: the tail (n>=4 region) was the
    // last thing reduce read, so it is resident in L2 when apply begins.
    for (int vr = base; vr < TOTAL_V4; vr += stride) {
        const int v = TOTAL_V4 - 1 - vr;        // descending addresses
        const int c = (v >> 15) & (NC - 1);     // SPATIAL/4 = 2^15 vec4 per slice
        const float4 p = sp[c];                 // {mean, inv_std, w, b}
        float4 xv = __ldcs(xin + v);            // dead after read: evict-first
        float2 a = fq2(xv.x, xv.y);
        float2 b = fq2(xv.z, xv.w);
        float y0 = fmaf(p.z, (a.x - p.x) * p.y, p.w);
        float y1 = fmaf(p.z, (a.y - p.x) * p.y, p.w);
        float y2 = fmaf(p.z, (b.x - p.x) * p.y, p.w);
        float y3 = fmaf(p.z, (b.y - p.x) * p.y, p.w);
        float2 q0 = fq2(y0, y1);
        float2 q1 = fq2(y2, y3);
        __stcs(yo + v, make_float4(q0.x, q0.y, q1.x, q1.y));
    }
}

extern "C" void kernel_launch(void* const* d_in, const int* in_sizes, int n_in,
                              void* d_out, int out_size) {
    const float* x      = (const float*)d_in[0];
    const float* weight = (const float*)d_in[1];
    const float* bias   = (const float*)d_in[2];
    float* out = (float*)d_out;

    dim3 rgrid(BPC, NC);
    qbn_reduce  <<<rgrid, RTHREADS>>>(x);
    qbn_finalize<<<NC, 32>>>(weight, bias);
    qbn_apply   <<<2048, 256>>>(x, out);
}